// round 10
// baseline (speedup 1.0000x reference)
#include <cuda_runtime.h>
#include <cuda_fp16.h>
#include <cstdint>

#define CIN   64
#define COUT  64
#define HH    224
#define WW    224
#define NB    16

// ---------------- smem layout (bytes) ----------------
// A: 770 position-rows x 128B (64 ci fp16), XOR swizzled (12-row strip).
#define A_OFF     0
#define A_ROWS    770
#define A_BYTES   (A_ROWS * 128)               // 98560
#define ALPHA_OFF (A_OFF + A_BYTES)
#define BIAS_OFF  (ALPHA_OFF + 256)
#define SMEM_TOTAL (BIAS_OFF + 256)            // 99072

// Plain ternary pattern [tap][co][ci] (fp16, exact)
__device__ __half g_plain[9 * COUT * CIN];
// Analytic mma B fragments: [tap][n8group(8)][kc(4)][lane(32)] x uint2
__device__ uint2 g_wfrag[9 * 8 * 4 * 32];
__device__ float g_alpha[COUT];
// x pre-converted to fp16, NHWC: [n][h][w][ci]
__device__ __half g_xh[(size_t)NB * HH * WW * CIN];

// ---------------------------------------------------------------------------
// Kernel 1: ternarize -> fp16 {-1,0,+1} pattern + per-cout alpha
// ---------------------------------------------------------------------------
__global__ void ternarize_kernel(const float* __restrict__ w) {
    __shared__ float red[256];
    __shared__ float red2[256];
    const int co  = blockIdx.x;
    const int tid = threadIdx.x;
    const float* wf = w + co * 576;

    float s = 0.f;
    for (int i = tid; i < 576; i += 256) s += fabsf(wf[i]);
    red[tid] = s;
    __syncthreads();
    for (int o = 128; o > 0; o >>= 1) {
        if (tid < o) red[tid] += red[tid + o];
        __syncthreads();
    }
    const float delta = (0.7f / 576.f) * red[0];
    __syncthreads();

    float cnt = 0.f, ms = 0.f;
    for (int i = tid; i < 576; i += 256) {
        float a = fabsf(wf[i]);
        if (a > delta) { cnt += 1.f; ms += a; }
    }
    red[tid] = ms; red2[tid] = cnt;
    __syncthreads();
    for (int o = 128; o > 0; o >>= 1) {
        if (tid < o) { red[tid] += red[tid + o]; red2[tid] += red2[tid + o]; }
        __syncthreads();
    }
    float count = (red2[0] == 0.f) ? 1.f : red2[0];
    float alpha = fmaxf(red[0] / count, 1e-4f);
    if (tid == 0) g_alpha[co] = alpha;

    // w index: [co][ci][tap]; emit g_plain[tap][co][ci]
    for (int i = tid; i < 576; i += 256) {
        int ci  = i / 9;
        int tap = i - ci * 9;
        float v = wf[i];
        float t = (v > delta) ? 1.f : ((v < -delta) ? -1.f : 0.f);
        g_plain[tap * 4096 + co * 64 + ci] = __float2half_rn(t);
    }
}

// ---------------------------------------------------------------------------
// Kernel 1b: pack B fragments in mma.m16n8k16 per-lane layout.
// ---------------------------------------------------------------------------
__global__ void pack_wfrag_kernel() {
    int tid = blockIdx.x * 256 + threadIdx.x;      // 0..9215
    if (tid >= 9 * 8 * 4 * 32) return;
    int lane = tid & 31;
    int kc   = (tid >> 5) & 3;
    int g    = (tid >> 7) & 7;
    int tap  = tid >> 10;

    int co = g * 8 + (lane >> 2);
    int k0 = kc * 16 + 2 * (lane & 3);
    const __half* p = g_plain + tap * 4096 + co * 64;

    __half2 w0 = __halves2half2(p[k0],     p[k0 + 1]);
    __half2 w1 = __halves2half2(p[k0 + 8], p[k0 + 9]);
    uint2 v;
    v.x = *(const uint32_t*)&w0;
    v.y = *(const uint32_t*)&w1;
    g_wfrag[((tap * 8 + g) * 4 + kc) * 32 + lane] = v;
}

// ---------------------------------------------------------------------------
// Kernel 1c: x fp32 NCHW -> fp16 NHWC transpose (coalesced both sides).
// Block = one (n, h); 7 w-tiles of 32; smem tile[32 w][66 ci-pitch].
// ---------------------------------------------------------------------------
__global__ __launch_bounds__(256)
void transform_kernel(const float* __restrict__ x) {
    __shared__ __half tile[32][66];
    const int h = blockIdx.x;
    const int n = blockIdx.y;
    const int tid  = threadIdx.x;
    const int wid  = tid >> 5;
    const int lane = tid & 31;

    const float* xp = x + ((size_t)n * CIN) * HH * WW + (size_t)h * WW;
    __half* dst = g_xh + ((size_t)(n * HH + h)) * WW * 64;

    for (int wt = 0; wt < 7; wt++) {
        const int wb = wt * 32;
        // load: 8 iters x (8 warps = 8 ci) x 32 w ; LDG 128B coalesced,
        // STS stride 132B (33 words, odd) -> conflict-free
        #pragma unroll
        for (int it = 0; it < 8; it++) {
            int ci = it * 8 + wid;
            float v = __ldg(xp + (size_t)ci * HH * WW + wb + lane);
            tile[lane][ci] = __float2half_rn(v);
        }
        __syncthreads();
        // write: 4 iters, warp = fixed w, lanes sweep 32 ci-pairs (LDS.32
        // consecutive words; STG.32 coalesced 128B)
        #pragma unroll
        for (int it = 0; it < 4; it++) {
            int idx = it * 256 + tid;
            int w  = idx >> 5;
            int cp = idx & 31;
            uint32_t v = *(const uint32_t*)&tile[w][cp * 2];
            *(uint32_t*)(dst + (size_t)(wb + w) * 64 + cp * 2) = v;
        }
        __syncthreads();
    }
}

// ---------------------------------------------------------------------------
// Baseline-PTX helpers
// ---------------------------------------------------------------------------
__device__ __forceinline__ uint32_t smem_u32(const void* p) {
    uint32_t a;
    asm("{ .reg .u64 t; cvta.to.shared.u64 t, %1; cvt.u32.u64 %0, t; }" : "=r"(a) : "l"(p));
    return a;
}
__device__ __forceinline__ void ldsm_x4(uint32_t* r, uint32_t addr) {
    asm volatile("ldmatrix.sync.aligned.m8n8.x4.shared.b16 {%0,%1,%2,%3}, [%4];"
                 : "=r"(r[0]), "=r"(r[1]), "=r"(r[2]), "=r"(r[3]) : "r"(addr));
}
__device__ __forceinline__ void mma16816(float* d, const uint32_t* a, const uint32_t* b) {
    asm volatile("mma.sync.aligned.m16n8k16.row.col.f32.f16.f16.f32 "
                 "{%0,%1,%2,%3}, {%4,%5,%6,%7}, {%8,%9}, {%0,%1,%2,%3};"
                 : "+f"(d[0]), "+f"(d[1]), "+f"(d[2]), "+f"(d[3])
                 : "r"(a[0]), "r"(a[1]), "r"(a[2]), "r"(a[3]), "r"(b[0]), "r"(b[1]));
}
__device__ __forceinline__ void cpasync16(uint32_t dst, const void* src) {
    asm volatile("cp.async.cg.shared.global [%0], [%1], 16;" :: "r"(dst), "l"(src) : "memory");
}

// ---------------------------------------------------------------------------
// Kernel 2: fp16 mma.sync implicit conv, 256 threads, 2 CTAs/SM.
// CTA strip: 12 input rows x 64 cols (10x62 valid outputs), positions
// 0..767 in smem rows 1..768 (+ zero guards 0, 769). 5 M=128 tiles x N=64.
// A staged via cp.async from pre-converted NHWC fp16 (one 128B row per pos).
// 8 warps: warp tile m32 (wid&3) x n32 (wid>>2); B frags via LDG (L1-hot).
// ---------------------------------------------------------------------------
__global__ __launch_bounds__(256, 2)
void conv_mma_kernel(const float* __restrict__ bias,
                     float* __restrict__ out) {
    extern __shared__ char smem[];
    const uint32_t sb  = smem_u32(smem);
    const int tid  = threadIdx.x;
    const int wid  = tid >> 5;
    const int lane = tid & 31;

    const int w0 = blockIdx.x * 62;
    const int h0 = blockIdx.y * 10;
    const int n  = blockIdx.z;

    if (tid < 64) {
        *(float*)(smem + ALPHA_OFF + tid * 4) = g_alpha[tid];
        *(float*)(smem + BIAS_OFF  + tid * 4) = __ldg(&bias[tid]);
    }
    // zero guard rows 0 and 769 (128B each = 8 uint4 per row)
    if (tid >= 64 && tid < 80) {
        int j = tid - 64;
        int off = (j < 8) ? j * 16 : (769 * 128 + (j - 8) * 16);
        *(uint4*)(smem + A_OFF + off) = make_uint4(0, 0, 0, 0);
    }

    // ---- stage A via cp.async: 768 positions x 8 octets (16B each)
    {
        const __half* xb = g_xh + ((size_t)n * HH) * WW * 64;
        #pragma unroll 4
        for (int i = tid; i < 768 * 8; i += 256) {
            int p = i >> 3;                 // 0..767
            int o = i & 7;
            int r = p >> 6, c = p & 63;
            int h = h0 + r - 1, w = w0 + c - 1;
            int row = p + 1;
            uint32_t dst = sb + A_OFF + (uint32_t)(row * 128)
                         + (uint32_t)(((o ^ (row & 7)) << 4));
            if ((unsigned)h < HH && (unsigned)w < WW) {
                cpasync16(dst, xb + ((size_t)h * WW + w) * 64 + o * 8);
            } else {
                *(uint4*)(smem + A_OFF + row * 128 + ((o ^ (row & 7)) << 4)) =
                    make_uint4(0, 0, 0, 0);
            }
        }
        asm volatile("cp.async.commit_group;" ::: "memory");
        asm volatile("cp.async.wait_group 0;" ::: "memory");
    }
    __syncthreads();

    // ---- compute
    const int wm  = wid & 3;         // 0..3 (M slice, m32)
    const int wn  = wid >> 2;        // 0..1 (N slice, n32)
    const int n0g = wn * 4;          // first n8-group

    const int a_row = lane & 15;
    const int a_uo  = lane >> 4;     // 0..1

    const float* al = (const float*)(smem + ALPHA_OFF);
    const float* bi = (const float*)(smem + BIAS_OFF);

    #pragma unroll 1
    for (int t = 0; t < 5; t++) {
        float acc[2][4][4];
        #pragma unroll
        for (int mc = 0; mc < 2; mc++)
            #pragma unroll
            for (int nc = 0; nc < 4; nc++)
                #pragma unroll
                for (int q = 0; q < 4; q++) acc[mc][nc][q] = 0.f;

        const int pt = 64 + t * 128 + wm * 32;

        #pragma unroll 1
        for (int tap = 0; tap < 9; tap++) {
            const int shift = (tap / 3) * 64 + (tap % 3) - 65;
            const uint2* wf = g_wfrag + (size_t)(tap * 8 + n0g) * 128 + lane;

            #pragma unroll
            for (int kc = 0; kc < 4; kc++) {
                uint2 bfr[4];
                #pragma unroll
                for (int nc = 0; nc < 4; nc++)
                    bfr[nc] = __ldg(wf + (nc * 4 + kc) * 32);

                #pragma unroll
                for (int mc = 0; mc < 2; mc++) {
                    int row = pt + mc * 16 + 1 + shift + a_row;
                    int u   = kc * 2 + a_uo;
                    uint32_t addr = sb + A_OFF + (uint32_t)(row * 128)
                                  + (uint32_t)((u ^ (row & 7)) << 4);
                    uint32_t afr[4];
                    ldsm_x4(afr, addr);
                    #pragma unroll
                    for (int nc = 0; nc < 4; nc++)
                        mma16816(acc[mc][nc], afr, (const uint32_t*)&bfr[nc]);
                }
            }
        }

        // ---- epilogue tile t: alpha*d + bias
        #pragma unroll
        for (int mc = 0; mc < 2; mc++) {
            #pragma unroll
            for (int rr = 0; rr < 2; rr++) {
                const int p = pt + mc * 16 + rr * 8 + (lane >> 2);
                const int c = p & 63, r = p >> 6;
                const int h = h0 + r - 1, w = w0 + c - 1;
                if (c >= 1 && c <= 62 && h < HH && w < WW) {
                    float* ob = out + (((size_t)n * COUT) * HH + h) * WW + w;
                    #pragma unroll
                    for (int nc = 0; nc < 4; nc++) {
                        const int co = wn * 32 + nc * 8 + 2 * (lane & 3);
                        float v0 = acc[mc][nc][rr * 2 + 0] * al[co]     + bi[co];
                        float v1 = acc[mc][nc][rr * 2 + 1] * al[co + 1] + bi[co + 1];
                        ob[(size_t)co       * HH * WW] = v0;
                        ob[(size_t)(co + 1) * HH * WW] = v1;
                    }
                }
            }
        }
    }
}

// ---------------------------------------------------------------------------
extern "C" void kernel_launch(void* const* d_in, const int* in_sizes, int n_in,
                              void* d_out, int out_size) {
    const float* x      = (const float*)d_in[0];
    const float* weight = (const float*)d_in[1];
    const float* bias   = (const float*)d_in[2];
    float* out          = (float*)d_out;

    cudaFuncSetAttribute(conv_mma_kernel,
                         cudaFuncAttributeMaxDynamicSharedMemorySize, SMEM_TOTAL);

    ternarize_kernel<<<COUT, 256>>>(weight);
    pack_wfrag_kernel<<<36, 256>>>();
    transform_kernel<<<dim3(HH, NB), 256>>>(x);
    dim3 grid(4, 23, NB);   // 4 W-strips (62 wide), 23 H-strips (10 tall), N=16
    conv_mma_kernel<<<grid, 256, SMEM_TOTAL>>>(bias, out);
}